// round 15
// baseline (speedup 1.0000x reference)
#include <cuda_runtime.h>
#include <cstdint>

// ToRGB split-K conv + epilogue, R15.
// vs R12 (best conv 110us, L1 38%, issue 59%):
//  1) shuffle-halo: 1 aligned LDS.128 per row; edge taps via shfl_up/shfl_down
//     (kills the two 4-way bank-conflicted scalar LDS per row).
//  2) no in-loop __syncthreads: 3-stage bulk ring with full(tx)/empty(16-arrive)
//     mbarriers -> warps get up to 3 iters of slack.
//  3) thread = 4 rows x 4 px x 3 co (R12 blocking), tile 64x128, CPS=1, split-K 8.

using ull = unsigned long long;

constexpr int TPB      = 512;
constexpr int HW       = 128;
constexpr int C_IN     = 512;
constexpr int C_PER    = 64;                           // channels per CTA (eighth)
constexpr int NSTAGE   = 3;
constexpr int NITER    = C_PER;                        // CPS=1 -> 64 iters
constexpr int TILE_ROWS= 66;                           // y0-1 .. y0+64
constexpr int ROW_BYTES= 512;                          // 128 floats, no halo
constexpr int CH_BYTES = TILE_ROWS * ROW_BYTES;        // 33792
constexpr int WCH_ULL  = 28;                           // 27 weights + pad
constexpr int WCH_BYTES= WCH_ULL * 8;                  // 224
constexpr int STAGE_BYTES = 34048;                     // 33792 + 224, padded to 64
constexpr unsigned MBAR_OFF   = NSTAGE * STAGE_BYTES;  // 102144
constexpr unsigned SMEM_BYTES = MBAR_OFF + 64;         // full[3] @ +0/8/16, empty[3] @ +24/32/40
constexpr uint32_t STAGE_TX = 65 * 512 + WCH_BYTES;    // 65 valid rows always (y0 in {0,64})

__device__ __align__(16) ull g_wdup[C_IN * WCH_ULL];
__device__ float g_part[8][8 * 3 * HW * HW];

__device__ __forceinline__ ull pack2(float lo, float hi) {
    ull r; asm("mov.b64 %0, {%1,%2};" : "=l"(r) : "f"(lo), "f"(hi)); return r;
}
__device__ __forceinline__ void unpack2(ull v, float& lo, float& hi) {
    asm("mov.b64 {%0,%1}, %2;" : "=f"(lo), "=f"(hi) : "l"(v));
}
__device__ __forceinline__ void ffma2(ull& d, ull a, ull b) {
    asm("fma.rn.f32x2 %0, %1, %2, %0;" : "+l"(d) : "l"(a), "l"(b));
}
__device__ __forceinline__ void bulk_cp(uint32_t dst, const void* src, uint32_t bytes,
                                        uint32_t mbar) {
    asm volatile("cp.async.bulk.shared::cluster.global.mbarrier::complete_tx::bytes "
                 "[%0], [%1], %2, [%3];"
                 :: "r"(dst), "l"(src), "r"(bytes), "r"(mbar) : "memory");
}
__device__ __forceinline__ void mbar_init(uint32_t mbar, uint32_t cnt) {
    asm volatile("mbarrier.init.shared.b64 [%0], %1;" :: "r"(mbar), "r"(cnt) : "memory");
}
__device__ __forceinline__ void mbar_expect_tx(uint32_t mbar, uint32_t bytes) {
    asm volatile("mbarrier.arrive.expect_tx.shared.b64 _, [%0], %1;"
                 :: "r"(mbar), "r"(bytes) : "memory");
}
__device__ __forceinline__ void mbar_arrive(uint32_t mbar) {
    asm volatile("mbarrier.arrive.shared.b64 _, [%0];" :: "r"(mbar) : "memory");
}
__device__ __forceinline__ void mbar_wait(uint32_t mbar, uint32_t parity) {
    asm volatile(
        "{\n\t"
        ".reg .pred P;\n\t"
        "WAIT_%=:\n\t"
        "mbarrier.try_wait.parity.acquire.cta.shared::cta.b64 P, [%0], %1, 0x989680;\n\t"
        "@P bra.uni DONE_%=;\n\t"
        "bra.uni WAIT_%=;\n\t"
        "DONE_%=:\n\t"
        "}" :: "r"(mbar), "r"(parity) : "memory");
}

// ---------------- k0: weight prep ----------------
__global__ void prep_kernel(const float* __restrict__ weight)
{
    int i = blockIdx.x * 256 + threadIdx.x;
    if (i >= C_IN * WCH_ULL) return;
    int c = i / WCH_ULL, slot = i % WCH_ULL;
    int co = slot / 9, k = slot % 9;       // co==3 -> pad slot
    float w = 0.f;
    if (co < 3)
        w = weight[(co * C_IN + c) * 9 + k] * (1.0f / sqrtf(4608.0f));
    g_wdup[i] = pack2(w, w);
}

// ---------------- dummy: aligns ncu capture (global launch #3) onto conv ------
__global__ void dummy_kernel() {}

// ---------------- k1: split-K conv ----------------
__global__ void __launch_bounds__(TPB, 1)
conv_kernel(const float* __restrict__ input)
{
    extern __shared__ char smem_raw[];
    float* tiles = reinterpret_cast<float*>(smem_raw);

    const int tid = threadIdx.x;
    const int tx4 = tid & 31;          // pixels 4*tx4 .. 4*tx4+3
    const int tyg = tid >> 5;          // 0..15: output rows y0 + 4*tyg + {0..3}
    const int b   = blockIdx.y;
    const int y0  = blockIdx.x * 64;
    const int qh  = blockIdx.z;        // channel eighth
    const int cbase = qh * C_PER;

    uint32_t tiles_u32 = (uint32_t)__cvta_generic_to_shared(tiles);
    uint32_t mb_full   = tiles_u32 + MBAR_OFF;        // +s*8
    uint32_t mb_empty  = tiles_u32 + MBAR_OFF + 24;   // +s*8

    // zero whole ring once (OOB row slots stay zero forever)
    for (int i = tid; i < (int)(NSTAGE * STAGE_BYTES / 16); i += TPB)
        reinterpret_cast<float4*>(smem_raw)[i] = make_float4(0.f, 0.f, 0.f, 0.f);
    if (tid < NSTAGE) {
        mbar_init(mb_full  + tid * 8, 1);
        mbar_init(mb_empty + tid * 8, 16);     // one arrive per warp
    }
    asm volatile("fence.proxy.async.shared::cta;" ::: "memory");
    __syncthreads();

    const char* in_b = reinterpret_cast<const char*>(input) + (size_t)b * C_IN * HW * HW * 4;
    const char* wgl  = reinterpret_cast<const char*>(g_wdup);

    // producer roles: tid<66 -> row tid; tid==66 -> weights
    const int  my_y    = y0 - 1 + tid;
    const bool my_data = (tid < TILE_ROWS) && (my_y >= 0) && (my_y < HW);
    const bool my_w    = (tid == TILE_ROWS);
    const uint32_t my_dst_off = (tid < TILE_ROWS) ? (uint32_t)(tid * ROW_BYTES)
                                                  : (uint32_t)CH_BYTES;

    auto issue_into = [&](int s, int nc) {     // producers only; empty already waited
        uint32_t sb = tiles_u32 + s * STAGE_BYTES;
        int ch = cbase + nc;
        if (tid == 0) mbar_expect_tx(mb_full + s * 8, STAGE_TX);
        if (my_data)
            bulk_cp(sb + my_dst_off,
                    in_b + (size_t)ch * (HW * HW * 4) + (size_t)my_y * ROW_BYTES,
                    ROW_BYTES, mb_full + s * 8);
        else if (my_w)
            bulk_cp(sb + my_dst_off, wgl + (size_t)ch * WCH_BYTES,
                    WCH_BYTES, mb_full + s * 8);
    };

    // prologue: fill stages 0..2 (no empty-wait needed)
    if (tid <= TILE_ROWS) {
        issue_into(0, 0);
        issue_into(1, 1);
        issue_into(2, 2);
    }

    ull acc[24];   // [co][od][half] -> (co*4+od)*2 + h
#pragma unroll
    for (int i = 0; i < 24; i++) acc[i] = 0ull;

    const bool is_lane0  = (tx4 == 0);
    const bool is_lane31 = (tx4 == 31);
    const int  trow0 = tyg * 4;

    int s = 0, fp = 0;
    for (int it = 0; it < NITER; it++) {
        mbar_wait(mb_full + s * 8, fp);

        const float* st = tiles + s * (STAGE_BYTES / 4);
        // this channel's 27 weights -> regs (14 broadcast LDS.128)
        ull w[28];
        {
            const ulonglong2* wp = reinterpret_cast<const ulonglong2*>(
                reinterpret_cast<const char*>(st) + CH_BYTES);
#pragma unroll
            for (int j = 0; j < 14; j++) {
                ulonglong2 v = wp[j];
                w[2 * j] = v.x; w[2 * j + 1] = v.y;
            }
        }
        const float* tp = st + trow0 * (ROW_BYTES / 4);
#pragma unroll
        for (int ir = 0; ir < 6; ir++) {       // tile rows trow0..trow0+5
            ulonglong2 cc = *reinterpret_cast<const ulonglong2*>(
                tp + ir * (ROW_BYTES / 4) + 4 * tx4);
            float c0, c1, c2, c3;
            unpack2(cc.x, c0, c1);
            unpack2(cc.y, c2, c3);
            float sl = __shfl_up_sync(0xffffffffu,  c3, 1);
            float rr = __shfl_down_sync(0xffffffffu, c0, 1);
            if (is_lane0)  sl = 0.f;    // implicit left halo
            if (is_lane31) rr = 0.f;    // implicit right halo
            ull P0 = cc.x, P1 = cc.y;
            ull A0 = pack2(sl, c0);
            ull A1 = pack2(c1, c2);
            ull C1 = pack2(c3, rr);
#pragma unroll
            for (int ky = 0; ky < 3; ky++) {
                int od = ir - ky;
                if (od < 0 || od > 3) continue;    // compile-time prune
#pragma unroll
                for (int co = 0; co < 3; co++) {
                    ull* a = &acc[(co * 4 + od) * 2];
                    const ull* wr = &w[co * 9 + ky * 3];
                    ffma2(a[0], wr[0], A0);
                    ffma2(a[1], wr[0], A1);
                    ffma2(a[0], wr[1], P0);
                    ffma2(a[1], wr[1], P1);
                    ffma2(a[0], wr[2], A1);   // C0 == A1
                    ffma2(a[1], wr[2], C1);
                }
            }
        }

        __syncwarp();
        if (tx4 == 0) mbar_arrive(mb_empty + s * 8);   // warp done with stage s

        int nc = it + NSTAGE;
        if (nc < NITER && tid <= TILE_ROWS) {
            mbar_wait(mb_empty + s * 8, fp);   // all 16 warps freed stage s
            issue_into(s, nc);
        }
        s++; if (s == NSTAGE) { s = 0; fp ^= 1; }
    }

#pragma unroll
    for (int co = 0; co < 3; co++)
#pragma unroll
        for (int od = 0; od < 4; od++) {
            int y = y0 + tyg * 4 + od;
            float l0, h0, l1, h1;
            unpack2(acc[(co * 4 + od) * 2 + 0], l0, h0);
            unpack2(acc[(co * 4 + od) * 2 + 1], l1, h1);
            float4 o; o.x = l0; o.y = h0; o.z = l1; o.w = h1;
            *reinterpret_cast<float4*>(
                &g_part[qh][(((size_t)(b * 3 + co) * HW + y) * HW) + 4 * tx4]) = o;
        }
}

// ---------------- k2: epilogue ----------------
__global__ void __launch_bounds__(256)
epilogue_kernel(const float* __restrict__ skip, const float* __restrict__ bias,
                float* __restrict__ out)
{
    int id = blockIdx.x * 256 + threadIdx.x;
    int xp = id & 63;
    int y  = (id >> 6) & 127;
    int p  = id >> 13;
    int b  = p / 3, co = p % 3;

    float2 s = make_float2(0.f, 0.f);
#pragma unroll
    for (int h = 0; h < 8; h++) {
        float2 v = reinterpret_cast<const float2*>(g_part[h])[id];
        s.x += v.x; s.y += v.y;
    }
    float bs = bias[co];

    const float* sk = skip + ((size_t)b * 3 + co) * 64 * 64;
    int syn = y >> 1;
    int syf = (y & 1) ? syn + 1 : syn - 1;
    float wyf = (syf >= 0 && syf < 64) ? 0.25f : 0.0f;
    int syfc = min(63, max(0, syf));
    const float* rn = sk + syn * 64;
    const float* rf = sk + syfc * 64;
    float cl_n = (xp > 0)  ? rn[xp - 1] : 0.f;
    float cc_n = rn[xp];
    float cr_n = (xp < 63) ? rn[xp + 1] : 0.f;
    float cl_f = (xp > 0)  ? rf[xp - 1] : 0.f;
    float cc_f = rf[xp];
    float cr_f = (xp < 63) ? rf[xp + 1] : 0.f;
    float rnx0 = 0.75f * cc_n + 0.25f * cl_n;
    float rnx1 = 0.75f * cc_n + 0.25f * cr_n;
    float rfx0 = 0.75f * cc_f + 0.25f * cl_f;
    float rfx1 = 0.75f * cc_f + 0.25f * cr_f;
    float sx0 = 0.75f * rnx0 + wyf * rfx0;
    float sx1 = 0.75f * rnx1 + wyf * rfx1;

    float2 o;
    o.x = s.x + bs + sx0;
    o.y = s.y + bs + sx1;
    reinterpret_cast<float2*>(out)[id] = o;
}

extern "C" void kernel_launch(void* const* d_in, const int* in_sizes, int n_in,
                              void* d_out, int out_size)
{
    const float* input  = (const float*)d_in[0];
    const float* skip   = (const float*)d_in[1];
    const float* weight = (const float*)d_in[2];
    const float* bias   = (const float*)d_in[3];
    float* out = (float*)d_out;

    cudaFuncSetAttribute(conv_kernel,
                         cudaFuncAttributeMaxDynamicSharedMemorySize, SMEM_BYTES);

    prep_kernel<<<(C_IN * WCH_ULL + 255) / 256, 256>>>(weight);   // launch 0
    dummy_kernel<<<1, 1>>>();                                     // launch 1
    dummy_kernel<<<1, 1>>>();                                     // launch 2
    dim3 grid(2, 8, 8);
    conv_kernel<<<grid, TPB, SMEM_BYTES>>>(input);                // launch 3 (ncu)
    epilogue_kernel<<<(8 * 3 * HW * HW / 2) / 256, 256>>>(skip, bias, out);
}